// round 4
// baseline (speedup 1.0000x reference)
#include <cuda_runtime.h>
#include <math.h>

#define NN  200000
#define KK  16
#define GG  4000
#define NPG 50
#define EPS 1e-5f

// ---------------- scratch ----------------
__device__ float g_B1[NN * 32];     // layer1 src-half messages, row stride 32 (128B line)
__device__ float g_D1[NN * 16];     // folded dst contribution layer1
__device__ float g_B2[NN * 16];     // layer2 src-half messages
__device__ float g_D2[NN * 8];      // folded dst contribution layer2
__device__ float g_pooled[GG * 8];  // graph pooling accumulators

// =================================================================
// kernel 1: ab1 — per-node B1 (25) and D1 (16); inline weight fold;
// also zeros g_pooled.
// =================================================================
__global__ void __launch_bounds__(256) ab1_kernel(
    const float* __restrict__ x,
    const float* __restrict__ w1_pre, const float* __restrict__ b1_pre,
    const float* __restrict__ w1_post, const float* __restrict__ b1_post,
    const float* __restrict__ w1_lin,  const float* __restrict__ b1_lin)
{
    __shared__ __align__(16) float xs[256 * 28];
    __shared__ __align__(16) float ws[25 * 28];
    __shared__ __align__(16) float cs[16 * 28];
    __shared__ float pa[16 * 25];
    __shared__ float pb[16 * 25];
    __shared__ float c0s[16];

    int t = threadIdx.x;
    int base = blockIdx.x * 256;
    int nvalid = NN - base; if (nvalid > 256) nvalid = 256;

    if (blockIdx.x < 125) g_pooled[blockIdx.x * 256 + t] = 0.f;

    for (int i = t; i < 16 * 25; i += 256) {
        int k = i / 25, jj = i % 25;
        const float* pr = w1_post + k * 300;
        pa[i] = pr[jj] + pr[25 + jj] + pr[50 + jj]
              + pr[100 + jj] + pr[125 + jj] + pr[150 + jj]
              + pr[200 + jj] + pr[225 + jj] + pr[250 + jj];
    }
    __syncthreads();
    for (int i = t; i < 16 * 25; i += 256) {
        int o = i / 25, jj = i % 25;
        float s = 0.f;
        for (int k = 0; k < 16; k++) s = fmaf(w1_lin[o * 16 + k], pa[k * 25 + jj], s);
        pb[i] = s;
    }
    __syncthreads();
    for (int i = t; i < 16 * 28; i += 256) {
        int o = i / 28, ii = i % 28;
        float s = 0.f;
        if (ii < 25) { for (int j = 0; j < 25; j++) s = fmaf(pb[o * 25 + j], w1_pre[j * 50 + ii], s); }
        cs[i] = s;
    }
    for (int i = t; i < 25 * 28; i += 256) {
        int j = i / 28, ii = i % 28;
        ws[i] = (ii < 25) ? w1_pre[j * 50 + 25 + ii] : 0.f;
    }
    if (t < 16) {
        float s = b1_lin[t];
        for (int k = 0; k < 16; k++) s = fmaf(w1_lin[t * 16 + k], b1_post[k], s);
        for (int j = 0; j < 25; j++) s = fmaf(pb[t * 25 + j], b1_pre[j], s);
        c0s[t] = s;
    }
    for (int i = t; i < nvalid * 25; i += 256) xs[(i / 25) * 28 + (i % 25)] = x[base * 25 + i];
    for (int i = t; i < nvalid * 3; i += 256) xs[(i / 3) * 28 + 25 + (i % 3)] = 0.f;
    __syncthreads();

    float b[25], d[16];
    bool act = (t < nvalid);
    if (act) {
        float4 xr[7];
        const float4* xp = (const float4*)&xs[t * 28];
#pragma unroll
        for (int i = 0; i < 7; i++) xr[i] = xp[i];
        const float4* wp = (const float4*)ws;
#pragma unroll
        for (int j = 0; j < 25; j++) {
            float4 a = make_float4(0.f, 0.f, 0.f, 0.f);
#pragma unroll
            for (int i = 0; i < 7; i++) {
                float4 w4 = wp[j * 7 + i];
                a.x = fmaf(w4.x, xr[i].x, a.x); a.y = fmaf(w4.y, xr[i].y, a.y);
                a.z = fmaf(w4.z, xr[i].z, a.z); a.w = fmaf(w4.w, xr[i].w, a.w);
            }
            b[j] = (a.x + a.y) + (a.z + a.w);
        }
        const float4* cp = (const float4*)cs;
#pragma unroll
        for (int o = 0; o < 16; o++) {
            float4 a = make_float4(0.f, 0.f, 0.f, 0.f);
#pragma unroll
            for (int i = 0; i < 7; i++) {
                float4 w4 = cp[o * 7 + i];
                a.x = fmaf(w4.x, xr[i].x, a.x); a.y = fmaf(w4.y, xr[i].y, a.y);
                a.z = fmaf(w4.z, xr[i].z, a.z); a.w = fmaf(w4.w, xr[i].w, a.w);
            }
            d[o] = c0s[o] + (a.x + a.y) + (a.z + a.w);
        }
    }
    __syncthreads();
    if (act) { for (int j = 0; j < 25; j++) xs[t * 28 + j] = b[j]; }
    __syncthreads();
    for (int i = t; i < nvalid * 32; i += 256) {
        int nd = i >> 5, c = i & 31;
        if (c < 25) g_B1[(base + nd) * 32 + c] = xs[nd * 28 + c];
    }
    __syncthreads();
    if (act) { for (int o = 0; o < 16; o++) xs[t * 16 + o] = d[o]; }
    __syncthreads();
    for (int i = t; i < nvalid * 16; i += 256) g_D1[base * 16 + i] = xs[i];
}

// =================================================================
// kernel 2: conv1 — W held in registers per lane; gather B1, stats,
// matvec -> h1 (smem only), fused ab2 -> B2/D2. Persistent grid.
// =================================================================
__global__ void __launch_bounds__(256) conv1_kernel(
    const int* __restrict__ src,
    const float* __restrict__ w1_post, const float* __restrict__ w1_lin,
    const float* __restrict__ w2_pre, const float* __restrict__ b2_pre,
    const float* __restrict__ w2_post, const float* __restrict__ b2_post,
    const float* __restrict__ w2_lin,  const float* __restrict__ b2_lin)
{
    __shared__ float s_pa[16 * 100];
    __shared__ __align__(16) float s_w1[16 * 104];   // packed [mean|min|max|std] + 4 zero pad
    __shared__ __align__(16) float s_agg[8][112];    // cols 0..103 used; 100..103 stay 0
    __shared__ __align__(16) float4 s_wb[4 * 32];
    __shared__ __align__(16) float s_h1[8][16];
    __shared__ float s_p92[8 * 16];
    __shared__ float s_wa2[8 * 16];
    __shared__ float s_c2m[8 * 16];
    __shared__ float s_c02[8];

    int t = threadIdx.x;
    // ---- fold layer1 W (packed) ----
    for (int i = t; i < 16 * 100; i += 256) {
        int k = i / 100, j = i % 100;
        s_pa[i] = w1_post[k * 300 + j] + w1_post[k * 300 + 100 + j] + w1_post[k * 300 + 200 + j];
    }
    for (int i = t; i < 8 * 16; i += 256) {
        int k = i / 16, jj = i % 16;
        const float* pr = w2_post + k * 192;
        s_p92[i] = pr[jj] + pr[16 + jj] + pr[32 + jj]
                 + pr[64 + jj] + pr[80 + jj] + pr[96 + jj]
                 + pr[128 + jj] + pr[144 + jj] + pr[160 + jj];
    }
    for (int i = t; i < 8 * 112; i += 256) ((float*)s_agg)[i] = 0.f;
    __syncthreads();
    for (int i = t; i < 16 * 104; i += 256) {
        int o = i / 104, j = i % 104;
        float s = 0.f;
        if (j < 100) { for (int k = 0; k < 16; k++) s = fmaf(w1_lin[o * 16 + k], s_pa[k * 100 + j], s); }
        s_w1[i] = s;
    }
    for (int i = t; i < 8 * 16; i += 256) {
        int o = i / 16, jj = i % 16;
        float s = 0.f;
        for (int k = 0; k < 8; k++) s = fmaf(w2_lin[o * 8 + k], s_p92[k * 16 + jj], s);
        s_wa2[i] = s;
    }
    __syncthreads();
    for (int i = t; i < 8 * 16; i += 256) {
        int o = i / 16, ii = i % 16;
        float s = 0.f;
        for (int j = 0; j < 16; j++) s = fmaf(s_wa2[o * 16 + j], w2_pre[j * 32 + ii], s);
        s_c2m[i] = s;
    }
    if (t < 8) {
        float s = b2_lin[t];
        for (int k = 0; k < 8; k++) s = fmaf(w2_lin[t * 8 + k], b2_post[k], s);
        for (int j = 0; j < 16; j++) s = fmaf(s_wa2[t * 16 + j], b2_pre[j], s);
        s_c02[t] = s;
    }
    __syncthreads();
    for (int i = t; i < 4 * 32; i += 256) {
        int i4 = i / 32, l = i % 32;
        float4 v = make_float4(0.f, 0.f, 0.f, 0.f);
        if (l < 16) {
            v.x = w2_pre[l * 32 + 16 + i4 * 4 + 0];
            v.y = w2_pre[l * 32 + 16 + i4 * 4 + 1];
            v.z = w2_pre[l * 32 + 16 + i4 * 4 + 2];
            v.w = w2_pre[l * 32 + 16 + i4 * 4 + 3];
        } else if (l < 24) {
            int o = l - 16;
            v.x = s_c2m[o * 16 + i4 * 4 + 0];
            v.y = s_c2m[o * 16 + i4 * 4 + 1];
            v.z = s_c2m[o * 16 + i4 * 4 + 2];
            v.w = s_c2m[o * 16 + i4 * 4 + 3];
        }
        s_wb[i] = v;
    }
    __syncthreads();

    int w = t >> 5, lane = t & 31;
    int o = lane & 15, hf = lane >> 4;

    // W slice into registers: 13 float4 = 52 floats per lane
    float4 Wr[13];
    {
        const float4* wrow = (const float4*)&s_w1[o * 104 + hf * 52];
#pragma unroll
        for (int j = 0; j < 13; j++) Wr[j] = wrow[j];
    }

    for (int grp = blockIdx.x; grp < NN / 8; grp += gridDim.x) {
        int n = grp * 8 + w;
        float d1v = (lane < 16) ? __ldg(&g_D1[n * 16 + lane]) : 0.f;
        int sv = __ldg(&src[n * 16 + (lane & 15)]);
        float sum = 0.f, sq = 0.f, mn = 1e30f, mx = -1e30f;
#pragma unroll
        for (int e = 0; e < 16; e++) {
            int s = __shfl_sync(0xffffffffu, sv, e);
            float bv = __ldg(&g_B1[s * 32 + lane]);
            sum += bv; sq = fmaf(bv, bv, sq);
            mn = fminf(mn, bv); mx = fmaxf(mx, bv);
        }
        if (lane < 25) {
            float mean = sum * (1.f / 16.f), m2 = sq * (1.f / 16.f);
            float st = sqrtf(fmaxf(m2 - mean * mean, 0.f) + EPS);
            s_agg[w][lane]      = mean;
            s_agg[w][25 + lane] = mn;
            s_agg[w][50 + lane] = mx;
            s_agg[w][75 + lane] = st;
        }
        __syncwarp();
        // matvec: lane (o,hf) -> partial dot over its 52 columns
        {
            const float4* ar = (const float4*)&s_agg[w][hf * 52];
            float4 a4 = make_float4(0.f, 0.f, 0.f, 0.f);
#pragma unroll
            for (int j = 0; j < 13; j++) {
                float4 av = ar[j];
                a4.x = fmaf(Wr[j].x, av.x, a4.x); a4.y = fmaf(Wr[j].y, av.y, a4.y);
                a4.z = fmaf(Wr[j].z, av.z, a4.z); a4.w = fmaf(Wr[j].w, av.w, a4.w);
            }
            float p = (a4.x + a4.y) + (a4.z + a4.w);
            p += __shfl_xor_sync(0xffffffffu, p, 16);
            if (lane < 16) s_h1[w][lane] = fmaxf(p + d1v, 0.f);
        }
        __syncwarp();
        // fused ab2: lanes 0-15 -> B2, lanes 16-23 -> D2
        {
            float acc = (lane >= 16 && lane < 24) ? s_c02[lane - 16] : 0.f;
            const float4* h4 = (const float4*)&s_h1[w][0];
#pragma unroll
            for (int i4 = 0; i4 < 4; i4++) {
                float4 hv = h4[i4];
                float4 wv = s_wb[i4 * 32 + lane];
                acc = fmaf(wv.x, hv.x, acc); acc = fmaf(wv.y, hv.y, acc);
                acc = fmaf(wv.z, hv.z, acc); acc = fmaf(wv.w, hv.w, acc);
            }
            if (lane < 16)      g_B2[n * 16 + lane] = acc;
            else if (lane < 24) g_D2[n * 8 + lane - 16] = acc;
        }
        __syncwarp();
    }
}

// =================================================================
// kernel 3: conv2 — 2 nodes/warp; W in registers; fused pooling.
// =================================================================
__global__ void __launch_bounds__(256) conv2_kernel(
    const int* __restrict__ src,
    const float* __restrict__ w2_post, const float* __restrict__ w2_lin)
{
    __shared__ float s_pa[8 * 64];
    __shared__ __align__(16) float s_w2[8 * 64];
    __shared__ __align__(16) float s_agg[8][2][72];  // per node: [mean16|min16|pad4|max16|std16|pad4]

    int t = threadIdx.x;
    for (int i = t; i < 8 * 64; i += 256) {
        int k = i / 64, j = i % 64;
        s_pa[i] = w2_post[k * 192 + j] + w2_post[k * 192 + 64 + j] + w2_post[k * 192 + 128 + j];
    }
    for (int i = t; i < 8 * 2 * 72; i += 256) ((float*)s_agg)[i] = 0.f;
    __syncthreads();
    for (int i = t; i < 8 * 64; i += 256) {
        int o = i / 64, j = i % 64;
        float s = 0.f;
        for (int k = 0; k < 8; k++) s = fmaf(w2_lin[o * 8 + k], s_pa[k * 64 + j], s);
        s_w2[i] = s;
    }
    __syncthreads();

    int w = t >> 5, lane = t & 31;
    int node = lane >> 4, r = lane & 15;
    int o = r >> 1, hf = r & 1;

    float4 Wr[8];
    {
        const float4* wrow = (const float4*)&s_w2[o * 64 + hf * 32];
#pragma unroll
        for (int j = 0; j < 8; j++) Wr[j] = wrow[j];
    }

    for (int grp = blockIdx.x; grp < NN / 16; grp += gridDim.x) {
        int nA = (grp * 8 + w) * 2;
        int n2 = nA + node;
        float d2v = (hf == 0) ? __ldg(&g_D2[n2 * 8 + o]) : 0.f;
        int sv = __ldg(&src[nA * 16 + lane]);
        float sum = 0.f, sq = 0.f, mn = 1e30f, mx = -1e30f;
#pragma unroll
        for (int e = 0; e < 16; e++) {
            int s = __shfl_sync(0xffffffffu, sv, e | (lane & 16));
            float bv = __ldg(&g_B2[s * 16 + (lane & 15)]);
            sum += bv; sq = fmaf(bv, bv, sq);
            mn = fminf(mn, bv); mx = fmaxf(mx, bv);
        }
        {
            float mean = sum * (1.f / 16.f), m2 = sq * (1.f / 16.f);
            float st = sqrtf(fmaxf(m2 - mean * mean, 0.f) + EPS);
            int nd = lane >> 4, f = lane & 15;
            s_agg[w][nd][f]      = mean;
            s_agg[w][nd][16 + f] = mn;
            s_agg[w][nd][36 + f] = mx;
            s_agg[w][nd][52 + f] = st;
        }
        __syncwarp();
        {
            const float4* ar = (const float4*)&s_agg[w][node][hf * 36];
            float4 a4 = make_float4(0.f, 0.f, 0.f, 0.f);
#pragma unroll
            for (int j = 0; j < 8; j++) {
                float4 av = ar[j];
                a4.x = fmaf(Wr[j].x, av.x, a4.x); a4.y = fmaf(Wr[j].y, av.y, a4.y);
                a4.z = fmaf(Wr[j].z, av.z, a4.z); a4.w = fmaf(Wr[j].w, av.w, a4.w);
            }
            float p = (a4.x + a4.y) + (a4.z + a4.w);
            p += __shfl_xor_sync(0xffffffffu, p, 1);
            if (hf == 0) {
                float h = fmaxf(p + d2v, 0.f);
                atomicAdd(&g_pooled[(n2 / NPG) * 8 + o], h);
            }
        }
        __syncwarp();
    }
}

// =================================================================
// kernel 4: FC + log_softmax per graph
// =================================================================
__global__ void final_kernel(const float* __restrict__ fc_w,
                             const float* __restrict__ fc_b,
                             float* __restrict__ out)
{
    int g = blockIdx.x * 256 + threadIdx.x;
    if (g >= GG) return;
    float l0 = fc_b[0], l1 = fc_b[1];
#pragma unroll
    for (int j = 0; j < 8; j++) {
        float p = g_pooled[g * 8 + j];
        l0 = fmaf(p, fc_w[j], l0);
        l1 = fmaf(p, fc_w[8 + j], l1);
    }
    float m = fmaxf(l0, l1);
    float lse = m + logf(expf(l0 - m) + expf(l1 - m));
    out[g * 2 + 0] = l0 - lse;
    out[g * 2 + 1] = l1 - lse;
}

// ---------------- launch ----------------
extern "C" void kernel_launch(void* const* d_in, const int* in_sizes, int n_in,
                              void* d_out, int out_size)
{
    const float* x       = (const float*)d_in[0];
    const int*   src     = (const int*)d_in[1];
    const float* w1_pre  = (const float*)d_in[3];
    const float* b1_pre  = (const float*)d_in[4];
    const float* w1_post = (const float*)d_in[5];
    const float* b1_post = (const float*)d_in[6];
    const float* w1_lin  = (const float*)d_in[7];
    const float* b1_lin  = (const float*)d_in[8];
    const float* w2_pre  = (const float*)d_in[9];
    const float* b2_pre  = (const float*)d_in[10];
    const float* w2_post = (const float*)d_in[11];
    const float* b2_post = (const float*)d_in[12];
    const float* w2_lin  = (const float*)d_in[13];
    const float* b2_lin  = (const float*)d_in[14];
    const float* fc_w    = (const float*)d_in[15];
    const float* fc_b    = (const float*)d_in[16];
    float* out = (float*)d_out;

    ab1_kernel<<<(NN + 255) / 256, 256>>>(x, w1_pre, b1_pre, w1_post, b1_post, w1_lin, b1_lin);
    conv1_kernel<<<592, 256>>>(src, w1_post, w1_lin,
                               w2_pre, b2_pre, w2_post, b2_post, w2_lin, b2_lin);
    conv2_kernel<<<592, 256>>>(src, w2_post, w2_lin);
    final_kernel<<<(GG + 255) / 256, 256>>>(fc_w, fc_b, out);
}

// round 5
// speedup vs baseline: 1.2341x; 1.2341x over previous
#include <cuda_runtime.h>
#include <math.h>

#define NN  200000
#define KK  16
#define GG  4000
#define NPG 50
#define EPS 1e-5f

// ---------------- scratch ----------------
__device__ float g_B1[NN * 32];     // layer1 src-half messages, row stride 32 (128B line)
__device__ float g_D1[NN * 16];     // folded dst contribution layer1
__device__ float g_B2[NN * 16];     // layer2 src-half messages
__device__ float g_D2[NN * 8];      // folded dst contribution layer2
__device__ float g_pooled[GG * 8];  // graph pooling accumulators

// =================================================================
// kernel 1: ab1 — per-node B1 (25) and D1 (16); inline weight fold;
// also zeros g_pooled.
// =================================================================
__global__ void __launch_bounds__(256) ab1_kernel(
    const float* __restrict__ x,
    const float* __restrict__ w1_pre, const float* __restrict__ b1_pre,
    const float* __restrict__ w1_post, const float* __restrict__ b1_post,
    const float* __restrict__ w1_lin,  const float* __restrict__ b1_lin)
{
    __shared__ __align__(16) float xs[256 * 28];
    __shared__ __align__(16) float ws[25 * 28];
    __shared__ __align__(16) float cs[16 * 28];
    __shared__ float pa[16 * 25];
    __shared__ float pb[16 * 25];
    __shared__ float c0s[16];

    int t = threadIdx.x;
    int base = blockIdx.x * 256;
    int nvalid = NN - base; if (nvalid > 256) nvalid = 256;

    if (blockIdx.x < 125) g_pooled[blockIdx.x * 256 + t] = 0.f;

    for (int i = t; i < 16 * 25; i += 256) {
        int k = i / 25, jj = i % 25;
        const float* pr = w1_post + k * 300;
        pa[i] = pr[jj] + pr[25 + jj] + pr[50 + jj]
              + pr[100 + jj] + pr[125 + jj] + pr[150 + jj]
              + pr[200 + jj] + pr[225 + jj] + pr[250 + jj];
    }
    __syncthreads();
    for (int i = t; i < 16 * 25; i += 256) {
        int o = i / 25, jj = i % 25;
        float s = 0.f;
        for (int k = 0; k < 16; k++) s = fmaf(w1_lin[o * 16 + k], pa[k * 25 + jj], s);
        pb[i] = s;
    }
    __syncthreads();
    for (int i = t; i < 16 * 28; i += 256) {
        int o = i / 28, ii = i % 28;
        float s = 0.f;
        if (ii < 25) { for (int j = 0; j < 25; j++) s = fmaf(pb[o * 25 + j], w1_pre[j * 50 + ii], s); }
        cs[i] = s;
    }
    for (int i = t; i < 25 * 28; i += 256) {
        int j = i / 28, ii = i % 28;
        ws[i] = (ii < 25) ? w1_pre[j * 50 + 25 + ii] : 0.f;
    }
    if (t < 16) {
        float s = b1_lin[t];
        for (int k = 0; k < 16; k++) s = fmaf(w1_lin[t * 16 + k], b1_post[k], s);
        for (int j = 0; j < 25; j++) s = fmaf(pb[t * 25 + j], b1_pre[j], s);
        c0s[t] = s;
    }
    for (int i = t; i < nvalid * 25; i += 256) xs[(i / 25) * 28 + (i % 25)] = x[base * 25 + i];
    for (int i = t; i < nvalid * 3; i += 256) xs[(i / 3) * 28 + 25 + (i % 3)] = 0.f;
    __syncthreads();

    float b[25], d[16];
    bool act = (t < nvalid);
    if (act) {
        float4 xr[7];
        const float4* xp = (const float4*)&xs[t * 28];
#pragma unroll
        for (int i = 0; i < 7; i++) xr[i] = xp[i];
        const float4* wp = (const float4*)ws;
#pragma unroll
        for (int j = 0; j < 25; j++) {
            float4 a = make_float4(0.f, 0.f, 0.f, 0.f);
#pragma unroll
            for (int i = 0; i < 7; i++) {
                float4 w4 = wp[j * 7 + i];
                a.x = fmaf(w4.x, xr[i].x, a.x); a.y = fmaf(w4.y, xr[i].y, a.y);
                a.z = fmaf(w4.z, xr[i].z, a.z); a.w = fmaf(w4.w, xr[i].w, a.w);
            }
            b[j] = (a.x + a.y) + (a.z + a.w);
        }
        const float4* cp = (const float4*)cs;
#pragma unroll
        for (int o = 0; o < 16; o++) {
            float4 a = make_float4(0.f, 0.f, 0.f, 0.f);
#pragma unroll
            for (int i = 0; i < 7; i++) {
                float4 w4 = cp[o * 7 + i];
                a.x = fmaf(w4.x, xr[i].x, a.x); a.y = fmaf(w4.y, xr[i].y, a.y);
                a.z = fmaf(w4.z, xr[i].z, a.z); a.w = fmaf(w4.w, xr[i].w, a.w);
            }
            d[o] = c0s[o] + (a.x + a.y) + (a.z + a.w);
        }
    }
    __syncthreads();
    if (act) { for (int j = 0; j < 25; j++) xs[t * 28 + j] = b[j]; }
    __syncthreads();
    for (int i = t; i < nvalid * 32; i += 256) {
        int nd = i >> 5, c = i & 31;
        if (c < 25) g_B1[(base + nd) * 32 + c] = xs[nd * 28 + c];
    }
    __syncthreads();
    if (act) { for (int o = 0; o < 16; o++) xs[t * 16 + o] = d[o]; }
    __syncthreads();
    for (int i = t; i < nvalid * 16; i += 256) g_D1[base * 16 + i] = xs[i];
}

// =================================================================
// kernel 2: conv1 — conflict-free smem W (stride 108); prefetched
// sv/D1; gather B1, stats, matvec -> h1 (smem), fused ab2 -> B2/D2.
// =================================================================
__global__ void __launch_bounds__(256, 4) conv1_kernel(
    const int* __restrict__ src,
    const float* __restrict__ w1_post, const float* __restrict__ w1_lin,
    const float* __restrict__ w2_pre, const float* __restrict__ b2_pre,
    const float* __restrict__ w2_post, const float* __restrict__ b2_post,
    const float* __restrict__ w2_lin,  const float* __restrict__ b2_lin)
{
    __shared__ float s_pa[16 * 100];
    __shared__ __align__(16) float s_w1[16 * 108];   // row: [mean25|min25|max25|std25|pad8], stride 108
    __shared__ __align__(16) float s_agg[8][112];    // cols 0..99 live, 100..111 zero
    __shared__ __align__(16) float4 s_wb[4 * 32];
    __shared__ __align__(16) float s_h1[8][16];
    __shared__ float s_p92[8 * 16];
    __shared__ float s_wa2[8 * 16];
    __shared__ float s_c2m[8 * 16];
    __shared__ float s_c02[8];

    int t = threadIdx.x;
    // ---- fold layer1 W ----
    for (int i = t; i < 16 * 100; i += 256) {
        int k = i / 100, j = i % 100;
        s_pa[i] = w1_post[k * 300 + j] + w1_post[k * 300 + 100 + j] + w1_post[k * 300 + 200 + j];
    }
    for (int i = t; i < 8 * 16; i += 256) {
        int k = i / 16, jj = i % 16;
        const float* pr = w2_post + k * 192;
        s_p92[i] = pr[jj] + pr[16 + jj] + pr[32 + jj]
                 + pr[64 + jj] + pr[80 + jj] + pr[96 + jj]
                 + pr[128 + jj] + pr[144 + jj] + pr[160 + jj];
    }
    for (int i = t; i < 8 * 112; i += 256) ((float*)s_agg)[i] = 0.f;
    __syncthreads();
    for (int i = t; i < 16 * 108; i += 256) {
        int o = i / 108, j = i % 108;
        float s = 0.f;
        if (j < 100) { for (int k = 0; k < 16; k++) s = fmaf(w1_lin[o * 16 + k], s_pa[k * 100 + j], s); }
        s_w1[i] = s;
    }
    for (int i = t; i < 8 * 16; i += 256) {
        int o = i / 16, jj = i % 16;
        float s = 0.f;
        for (int k = 0; k < 8; k++) s = fmaf(w2_lin[o * 8 + k], s_p92[k * 16 + jj], s);
        s_wa2[i] = s;
    }
    __syncthreads();
    for (int i = t; i < 8 * 16; i += 256) {
        int o = i / 16, ii = i % 16;
        float s = 0.f;
        for (int j = 0; j < 16; j++) s = fmaf(s_wa2[o * 16 + j], w2_pre[j * 32 + ii], s);
        s_c2m[i] = s;
    }
    if (t < 8) {
        float s = b2_lin[t];
        for (int k = 0; k < 8; k++) s = fmaf(w2_lin[t * 8 + k], b2_post[k], s);
        for (int j = 0; j < 16; j++) s = fmaf(s_wa2[t * 16 + j], b2_pre[j], s);
        s_c02[t] = s;
    }
    __syncthreads();
    for (int i = t; i < 4 * 32; i += 256) {
        int i4 = i / 32, l = i % 32;
        float4 v = make_float4(0.f, 0.f, 0.f, 0.f);
        if (l < 16) {
            v.x = w2_pre[l * 32 + 16 + i4 * 4 + 0];
            v.y = w2_pre[l * 32 + 16 + i4 * 4 + 1];
            v.z = w2_pre[l * 32 + 16 + i4 * 4 + 2];
            v.w = w2_pre[l * 32 + 16 + i4 * 4 + 3];
        } else if (l < 24) {
            int o = l - 16;
            v.x = s_c2m[o * 16 + i4 * 4 + 0];
            v.y = s_c2m[o * 16 + i4 * 4 + 1];
            v.z = s_c2m[o * 16 + i4 * 4 + 2];
            v.w = s_c2m[o * 16 + i4 * 4 + 3];
        }
        s_wb[i] = v;
    }
    __syncthreads();

    int w = t >> 5, lane = t & 31;
    int o = lane & 15, hf = lane >> 4;
    const float4* wr = (const float4*)&s_w1[o * 108 + hf * 52];

    // prefetch first iteration's scalars
    int grp = blockIdx.x;
    int sv = 0; float d1v = 0.f;
    if (grp < NN / 8) {
        int n0 = grp * 8 + w;
        sv = __ldg(&src[n0 * 16 + (lane & 15)]);
        d1v = (lane < 16) ? __ldg(&g_D1[n0 * 16 + lane]) : 0.f;
    }

    for (; grp < NN / 8; ) {
        int n = grp * 8 + w;
        int sv_c = sv; float d1_c = d1v;
        grp += gridDim.x;
        if (grp < NN / 8) {                       // prefetch next
            int nn = grp * 8 + w;
            sv = __ldg(&src[nn * 16 + (lane & 15)]);
            d1v = (lane < 16) ? __ldg(&g_D1[nn * 16 + lane]) : 0.f;
        }

        float sum = 0.f, sq = 0.f, mn = 1e30f, mx = -1e30f;
#pragma unroll
        for (int e = 0; e < 16; e++) {
            int s = __shfl_sync(0xffffffffu, sv_c, e);
            float bv = __ldg(&g_B1[s * 32 + lane]);   // lanes 25-31 read junk, unused
            sum += bv; sq = fmaf(bv, bv, sq);
            mn = fminf(mn, bv); mx = fmaxf(mx, bv);
        }
        if (lane < 25) {
            float mean = sum * (1.f / 16.f), m2 = sq * (1.f / 16.f);
            float st = sqrtf(fmaxf(m2 - mean * mean, 0.f) + EPS);
            s_agg[w][lane]      = mean;
            s_agg[w][25 + lane] = mn;
            s_agg[w][50 + lane] = mx;
            s_agg[w][75 + lane] = st;
        }
        __syncwarp();
        {
            const float4* ar = (const float4*)&s_agg[w][hf * 52];
            float4 a4 = make_float4(0.f, 0.f, 0.f, 0.f);
#pragma unroll
            for (int j = 0; j < 13; j++) {
                float4 wv = wr[j], av = ar[j];
                a4.x = fmaf(wv.x, av.x, a4.x); a4.y = fmaf(wv.y, av.y, a4.y);
                a4.z = fmaf(wv.z, av.z, a4.z); a4.w = fmaf(wv.w, av.w, a4.w);
            }
            float p = (a4.x + a4.y) + (a4.z + a4.w);
            p += __shfl_xor_sync(0xffffffffu, p, 16);
            if (lane < 16) s_h1[w][lane] = fmaxf(p + d1_c, 0.f);
        }
        __syncwarp();
        {
            float acc = (lane >= 16 && lane < 24) ? s_c02[lane - 16] : 0.f;
            const float4* h4 = (const float4*)&s_h1[w][0];
#pragma unroll
            for (int i4 = 0; i4 < 4; i4++) {
                float4 hv = h4[i4];
                float4 wv = s_wb[i4 * 32 + lane];
                acc = fmaf(wv.x, hv.x, acc); acc = fmaf(wv.y, hv.y, acc);
                acc = fmaf(wv.z, hv.z, acc); acc = fmaf(wv.w, hv.w, acc);
            }
            if (lane < 16)      g_B2[n * 16 + lane] = acc;
            else if (lane < 24) g_D2[n * 8 + lane - 16] = acc;
        }
        __syncwarp();
    }
}

// =================================================================
// kernel 3: conv2 — 2 nodes/warp; conflict-free smem W (stride 72);
// prefetched sv/D2; fused pooling.
// =================================================================
__global__ void __launch_bounds__(256, 4) conv2_kernel(
    const int* __restrict__ src,
    const float* __restrict__ w2_post, const float* __restrict__ w2_lin)
{
    __shared__ float s_pa[8 * 64];
    __shared__ __align__(16) float s_w2[8 * 72];     // row: [mean16|min16|pad4|max16|std16|pad4]
    __shared__ __align__(16) float s_agg[8][2][72];  // same internal layout per node

    int t = threadIdx.x;
    for (int i = t; i < 8 * 64; i += 256) {
        int k = i / 64, j = i % 64;
        s_pa[i] = w2_post[k * 192 + j] + w2_post[k * 192 + 64 + j] + w2_post[k * 192 + 128 + j];
    }
    for (int i = t; i < 8 * 72; i += 256) s_w2[i] = 0.f;
    for (int i = t; i < 8 * 2 * 72; i += 256) ((float*)s_agg)[i] = 0.f;
    __syncthreads();
    for (int i = t; i < 8 * 64; i += 256) {
        int o = i / 64, j = i % 64;
        float s = 0.f;
        for (int k = 0; k < 8; k++) s = fmaf(w2_lin[o * 8 + k], s_pa[k * 64 + j], s);
        int b = j >> 4, r = j & 15;
        const int off[4] = {0, 16, 36, 52};
        s_w2[o * 72 + off[b] + r] = s;
    }
    __syncthreads();

    int w = t >> 5, lane = t & 31;
    int node = lane >> 4, r = lane & 15;
    int o = r >> 1, hf = r & 1;
    const float4* wr = (const float4*)&s_w2[o * 72 + hf * 36];

    int grp = blockIdx.x;
    int sv = 0; float d2v = 0.f;
    if (grp < NN / 16) {
        int nA = (grp * 8 + w) * 2;
        sv = __ldg(&src[nA * 16 + lane]);
        d2v = (hf == 0) ? __ldg(&g_D2[(nA + node) * 8 + o]) : 0.f;
    }

    for (; grp < NN / 16; ) {
        int nA = (grp * 8 + w) * 2;
        int sv_c = sv; float d2_c = d2v;
        grp += gridDim.x;
        if (grp < NN / 16) {
            int nB = (grp * 8 + w) * 2;
            sv = __ldg(&src[nB * 16 + lane]);
            d2v = (hf == 0) ? __ldg(&g_D2[(nB + node) * 8 + o]) : 0.f;
        }

        float sum = 0.f, sq = 0.f, mn = 1e30f, mx = -1e30f;
#pragma unroll
        for (int e = 0; e < 16; e++) {
            int s = __shfl_sync(0xffffffffu, sv_c, e | (lane & 16));
            float bv = __ldg(&g_B2[s * 16 + (lane & 15)]);
            sum += bv; sq = fmaf(bv, bv, sq);
            mn = fminf(mn, bv); mx = fmaxf(mx, bv);
        }
        {
            float mean = sum * (1.f / 16.f), m2 = sq * (1.f / 16.f);
            float st = sqrtf(fmaxf(m2 - mean * mean, 0.f) + EPS);
            int nd = lane >> 4, f = lane & 15;
            s_agg[w][nd][f]      = mean;
            s_agg[w][nd][16 + f] = mn;
            s_agg[w][nd][36 + f] = mx;
            s_agg[w][nd][52 + f] = st;
        }
        __syncwarp();
        {
            const float4* ar = (const float4*)&s_agg[w][node][hf * 36];
            float4 a4 = make_float4(0.f, 0.f, 0.f, 0.f);
#pragma unroll
            for (int j = 0; j < 8; j++) {
                float4 wv = wr[j], av = ar[j];
                a4.x = fmaf(wv.x, av.x, a4.x); a4.y = fmaf(wv.y, av.y, a4.y);
                a4.z = fmaf(wv.z, av.z, a4.z); a4.w = fmaf(wv.w, av.w, a4.w);
            }
            float p = (a4.x + a4.y) + (a4.z + a4.w);
            p += __shfl_xor_sync(0xffffffffu, p, 1);
            if (hf == 0) {
                float h = fmaxf(p + d2_c, 0.f);
                atomicAdd(&g_pooled[((nA + node) / NPG) * 8 + o], h);
            }
        }
        __syncwarp();
    }
}

// =================================================================
// kernel 4: FC + log_softmax per graph
// =================================================================
__global__ void final_kernel(const float* __restrict__ fc_w,
                             const float* __restrict__ fc_b,
                             float* __restrict__ out)
{
    int g = blockIdx.x * 256 + threadIdx.x;
    if (g >= GG) return;
    float l0 = fc_b[0], l1 = fc_b[1];
#pragma unroll
    for (int j = 0; j < 8; j++) {
        float p = g_pooled[g * 8 + j];
        l0 = fmaf(p, fc_w[j], l0);
        l1 = fmaf(p, fc_w[8 + j], l1);
    }
    float m = fmaxf(l0, l1);
    float lse = m + logf(expf(l0 - m) + expf(l1 - m));
    out[g * 2 + 0] = l0 - lse;
    out[g * 2 + 1] = l1 - lse;
}

// ---------------- launch ----------------
extern "C" void kernel_launch(void* const* d_in, const int* in_sizes, int n_in,
                              void* d_out, int out_size)
{
    const float* x       = (const float*)d_in[0];
    const int*   src     = (const int*)d_in[1];
    const float* w1_pre  = (const float*)d_in[3];
    const float* b1_pre  = (const float*)d_in[4];
    const float* w1_post = (const float*)d_in[5];
    const float* b1_post = (const float*)d_in[6];
    const float* w1_lin  = (const float*)d_in[7];
    const float* b1_lin  = (const float*)d_in[8];
    const float* w2_pre  = (const float*)d_in[9];
    const float* b2_pre  = (const float*)d_in[10];
    const float* w2_post = (const float*)d_in[11];
    const float* b2_post = (const float*)d_in[12];
    const float* w2_lin  = (const float*)d_in[13];
    const float* b2_lin  = (const float*)d_in[14];
    const float* fc_w    = (const float*)d_in[15];
    const float* fc_b    = (const float*)d_in[16];
    float* out = (float*)d_out;

    ab1_kernel<<<(NN + 255) / 256, 256>>>(x, w1_pre, b1_pre, w1_post, b1_post, w1_lin, b1_lin);
    conv1_kernel<<<592, 256>>>(src, w1_post, w1_lin,
                               w2_pre, b2_pre, w2_post, b2_post, w2_lin, b2_lin);
    conv2_kernel<<<592, 256>>>(src, w2_post, w2_lin);
    final_kernel<<<(GG + 255) / 256, 256>>>(fc_w, fc_b, out);
}